// round 7
// baseline (speedup 1.0000x reference)
#include <cuda_runtime.h>

#define BB 32
#define LL 256
#define TT 1600
#define KK 80
#define PADV -1.0e12f

// ---- scratch (static device globals; no allocation) ----
__device__ float    g_lpT[BB * TT * LL];     // lp transposed [b][t][l]
__device__ float    g_A[BB * KK * LL];       // GEMM coeffs, k-major [b][k][l]
__device__ float    g_cst[BB * LL];          // per-(b,l) constant
__device__ unsigned g_D[BB * TT * 8];        // Viterbi decision bits, 256/(b,t)
__device__ int      g_path[BB * TT];         // chronological path rows (-1 = none)

// ============================================================
// K0: from mu_logvar [B][L][80] build
//   A[b, c   , l] = -0.0125 * invvar_c          (coeff for z^2)
//   A[b, 40+c, l] =  0.025  * mu_c * invvar_c   (coeff for z)
//   cst[b,l]      = -0.0125 * sum_c (mu^2*iv + logvar)
// ============================================================
__global__ void __launch_bounds__(256) k_prep(const float* __restrict__ mlv) {
    int warp = threadIdx.x >> 5, lane = threadIdx.x & 31;
    int row = blockIdx.x * 8 + warp;           // [0, B*L)
    int b = row >> 8, l = row & 255;
    const float* p = mlv + row * 80;

    float mu = p[lane], lv = p[40 + lane];
    float iv = expf(-lv);
    g_A[(b * KK + lane) * LL + l]      = -0.0125f * iv;
    g_A[(b * KK + 40 + lane) * LL + l] =  0.025f  * mu * iv;
    float acc = mu * mu * iv + lv;
    if (lane < 8) {
        float mu2 = p[32 + lane], lv2 = p[72 + lane];
        float iv2 = expf(-lv2);
        g_A[(b * KK + 32 + lane) * LL + l] = -0.0125f * iv2;
        g_A[(b * KK + 72 + lane) * LL + l] =  0.025f  * mu2 * iv2;
        acc += mu2 * mu2 * iv2 + lv2;
    }
#pragma unroll
    for (int o = 16; o; o >>= 1) acc += __shfl_down_sync(0xffffffffu, acc, o);
    if (!lane) g_cst[row] = -0.0125f * acc;
}

// ============================================================
// K1: lp[b,l,t] = sum_k A[b,k,l] * Z[b,k,t] + cst[b,l]
//   where Z = [z^2 ; z].  64x64 tile, 4x4 register blocking.
//   Writes lp [b][l][t] to d_out AND lpT [b][t][l] scratch.
// ============================================================
__global__ void __launch_bounds__(256) k_lp(const float* __restrict__ z,
                                            float* __restrict__ out_lp) {
    __shared__ float As[80][64];
    __shared__ float Zs[80][64];
    int b = blockIdx.z;
    int l0 = blockIdx.y << 6, t0 = blockIdx.x << 6;
    int tid = threadIdx.x;

    for (int i = tid; i < 80 * 64; i += 256)
        As[i >> 6][i & 63] = g_A[(b * KK + (i >> 6)) * LL + l0 + (i & 63)];
    for (int i = tid; i < 40 * 64; i += 256) {
        int c = i >> 6, t = i & 63;
        float zv = z[(b * 40 + c) * TT + t0 + t];
        Zs[c][t] = zv * zv;
        Zs[40 + c][t] = zv;
    }
    __syncthreads();

    int tx = tid & 15, ty = tid >> 4;
    float acc[4][4] = {};
#pragma unroll
    for (int k = 0; k < 80; k++) {
        float4 a  = *(const float4*)&As[k][ty << 2];
        float4 zz = *(const float4*)&Zs[k][tx << 2];
        acc[0][0] += a.x * zz.x; acc[0][1] += a.x * zz.y; acc[0][2] += a.x * zz.z; acc[0][3] += a.x * zz.w;
        acc[1][0] += a.y * zz.x; acc[1][1] += a.y * zz.y; acc[1][2] += a.y * zz.z; acc[1][3] += a.y * zz.w;
        acc[2][0] += a.z * zz.x; acc[2][1] += a.z * zz.y; acc[2][2] += a.z * zz.z; acc[2][3] += a.z * zz.w;
        acc[3][0] += a.w * zz.x; acc[3][1] += a.w * zz.y; acc[3][2] += a.w * zz.z; acc[3][3] += a.w * zz.w;
    }

    float cst[4];
#pragma unroll
    for (int i = 0; i < 4; i++) cst[i] = g_cst[b * LL + l0 + (ty << 2) + i];

#pragma unroll
    for (int i = 0; i < 4; i++) {
        int l = l0 + (ty << 2) + i;
        float4 v = make_float4(acc[i][0] + cst[i], acc[i][1] + cst[i],
                               acc[i][2] + cst[i], acc[i][3] + cst[i]);
        *(float4*)&out_lp[(size_t)(b * LL + l) * TT + t0 + (tx << 2)] = v;
    }
#pragma unroll
    for (int j = 0; j < 4; j++) {
        int t = t0 + (tx << 2) + j;
        float4 v = make_float4(acc[0][j] + cst[0], acc[1][j] + cst[1],
                               acc[2][j] + cst[2], acc[3][j] + cst[3]);
        *(float4*)&g_lpT[(size_t)(b * TT + t) * LL + l0 + (ty << 2)] = v;
    }
}

// ============================================================
// K2: fused forward DP (alpha, logaddexp) + Viterbi DP (beta, max).
//   Block = batch, thread j = text position. Double-buffered smem,
//   8-deep lp prefetch, 1 barrier/step.
//   D[b][t] bit l := beta[(l-1)%L][t] > beta[l][t]  (ballot).
// ============================================================
__global__ void __launch_bounds__(256) k_dp(const int* __restrict__ tl,
                                            const int* __restrict__ ml,
                                            float* __restrict__ out_loss) {
    __shared__ float sh_a[2][LL + 1];
    __shared__ float sh_b[2][LL + 1];
    int b = blockIdx.x, j = threadIdx.x;
    const float* lp = g_lpT + (size_t)b * TT * LL;
    int mlm1 = ml[b] - 1, tlm1 = tl[b] - 1;

    float lp00 = lp[0];
    float alpha = (j == 0) ? lp00 : PADV;
    float beta = alpha;
    if (j == 0) {
        sh_a[0][0] = PADV; sh_a[1][0] = PADV;
        sh_b[0][0] = PADV; sh_b[1][0] = PADV;
    }
    sh_a[0][j + 1] = alpha;
    sh_b[0][j + 1] = beta;
    float rec = 0.f;
    if (mlm1 == 0 && j == tlm1) rec = alpha;

    float lpbuf[8];
#pragma unroll
    for (int u = 0; u < 8; u++) lpbuf[u] = lp[(1 + u) * LL + j];
    int wj = ((j & 31) == 0);
    __syncthreads();

    for (int t0 = 1; t0 < TT; t0 += 8) {
#pragma unroll
        for (int u = 0; u < 8; u++) {
            int t = t0 + u;
            if (t >= TT) break;                 // uniform across block
            int cur = t & 1, prv = cur ^ 1;
            float am1 = sh_a[prv][j];                       // alpha[j-1] (pad @ j=0)
            float bm1 = sh_b[prv][j];                       // beta[j-1]  (pad @ j=0)
            float bwr = sh_b[prv][((j + 255) & 255) + 1];   // beta[(j-1)%256] wrap
            unsigned bal = __ballot_sync(0xffffffffu, bwr > beta);
            if (wj) g_D[(b * TT + (t - 1)) * 8 + (j >> 5)] = bal;

            float lpv = lpbuf[u];
            int tp = t + 8;
            lpbuf[u] = (tp < TT) ? lp[tp * LL + j] : 0.f;   // prefetch

            // alpha' = logaddexp(alpha+1e-7, alpha[j-1]+1e-7) + lp
            float s = alpha + 1e-7f;
            float g = am1 + 1e-7f;
            float mx = fmaxf(s, g);
            float e = __expf(-fabsf(s - g));
            alpha = mx + __logf(1.f + e) + lpv;
            // beta' = max(beta, beta[j-1]) + lp
            beta = fmaxf(beta, bm1) + lpv;

            sh_a[cur][j + 1] = alpha;
            sh_b[cur][j + 1] = beta;
            if (t == mlm1 && j == tlm1) rec = alpha;
            __syncthreads();
        }
    }
    {   // decision bits for last column (t = TT-1)
        int prv = (TT - 1) & 1;
        float bwr = sh_b[prv][((j + 255) & 255) + 1];
        unsigned bal = __ballot_sync(0xffffffffu, bwr > beta);
        if (wj) g_D[(b * TT + (TT - 1)) * 8 + (j >> 5)] = bal;
    }
    if (j == tlm1) out_loss[b] = -rec / (float)(mlm1 + 1);
}

// ============================================================
// K3: backtrace. Exact emulation of reference incl. %-wrap and
//   relu()-1 clamps (rows,cols saturate at -1). D staged in smem.
// ============================================================
__global__ void __launch_bounds__(256) k_bt(const int* __restrict__ tl,
                                            const int* __restrict__ ml) {
    extern __shared__ unsigned char s3raw[];
    unsigned* Dsh = (unsigned*)s3raw;                 // TT*8 words
    int* spath = (int*)(s3raw + TT * 8 * 4);          // TT ints
    int b = blockIdx.x, tid = threadIdx.x;
    const unsigned* Dg = g_D + (size_t)b * TT * 8;
    for (int i = tid; i < TT * 8; i += 256) Dsh[i] = Dg[i];
    for (int i = tid; i < TT; i += 256) spath[i] = -1;
    __syncthreads();

    if (tid == 0) {
        int mlv = ml[b];
        int r = tl[b] - 1, c = mlv - 1;
        spath[c] = r;                                 // k=0 -> t = ml-1
        for (int k = 1; k < TT; k++) {
            int lm = r & 255;                         // r >= -1: (-1)&255 = 255
            int cm = c - 1; if (cm < 0) cm += TT;     // (c-1) mod T, c >= -1
            unsigned w = Dsh[cm * 8 + (lm >> 5)];
            int go = (w >> (lm & 31)) & 1;            // val_go > val_stay
            r = max(r - go, -1);
            c = max(c, 0) - 1;
            int tc = mlv - 1 - k;
            if (tc >= 0) spath[tc] = r;
        }
    }
    __syncthreads();
    for (int i = tid; i < TT; i += 256) g_path[b * TT + i] = spath[i];
}

// ============================================================
// K4: alignment[b][t][l] = (l == path[b][t])  (warp per (b,t) row)
// ============================================================
__global__ void __launch_bounds__(256) k_align(float* __restrict__ out_align) {
    int gw = (blockIdx.x * 256 + threadIdx.x) >> 5;   // = b*T + t
    int lane = threadIdx.x & 31;
    int p = g_path[gw];
    int base = lane << 3;
    float4 lo = make_float4((float)(p == base),     (float)(p == base + 1),
                            (float)(p == base + 2), (float)(p == base + 3));
    float4 hi = make_float4((float)(p == base + 4), (float)(p == base + 5),
                            (float)(p == base + 6), (float)(p == base + 7));
    float* o = out_align + ((size_t)gw << 8) + base;
    *(float4*)o       = lo;
    *(float4*)(o + 4) = hi;
}

extern "C" void kernel_launch(void* const* d_in, const int* in_sizes, int n_in,
                              void* d_out, int out_size) {
    const float* mlv = (const float*)d_in[0];
    const float* z   = (const float*)d_in[1];
    const int*   tl  = (const int*)d_in[2];
    const int*   ml  = (const int*)d_in[3];

    float* out       = (float*)d_out;
    float* out_loss  = out;                                   // [32]
    float* out_align = out + 32;                              // [32,1600,256]
    float* out_lp    = out + 32 + (size_t)BB * TT * LL;       // [32,256,1600]

    k_prep<<<(BB * LL) / 8, 256>>>(mlv);
    k_lp<<<dim3(TT / 64, LL / 64, BB), 256>>>(z, out_lp);
    k_dp<<<BB, 256>>>(tl, ml, out_loss);

    int smem_bt = TT * 8 * 4 + TT * 4;                        // 57600 B
    cudaFuncSetAttribute(k_bt, cudaFuncAttributeMaxDynamicSharedMemorySize, smem_bt);
    k_bt<<<BB, 256, smem_bt>>>(tl, ml);

    k_align<<<(BB * TT * 32) / 256, 256>>>(out_align);
}